// round 9
// baseline (speedup 1.0000x reference)
#include <cuda_runtime.h>
#include <cuda_bf16.h>

// BBAStar: 8-connected grid shortest path, B=128, 32x32.
// R8: one warp per batch, lane = row, full row in registers.
// Horizontal GS sweeps are in-lane register chains (12 cyc/cell, no shfl on
// the chain). Vertical neighbor info enters via an off-chain pre[] (masked
// shfls + window-min). Vertical GS via smem transpose + same sweeps.
// Epoch = {row pre, L->R, R->L, transpose, col pre, T->B, B->T, transpose}:
// full-grid Gauss-Seidel in all 4 directions per epoch, warp-synchronous,
// convergence via __any_sync. Monotone relaxation with the exact reference
// operator fl(w + exact-min8) => bit-exact float fixed point of the
// reference's 1024 Jacobi sweeps; zero-change epoch => fixed point verified.
// Backtrack via precomputed argmin directions (OFFS first-occurrence tie-break).

#define BN 128
#define INF_F 1000000000.0f
#define EPS_F 1e-6f
#define FULLM 0xffffffffu

__device__ __forceinline__ int pick8(float a0, float a1, float a2, float a3,
                                     float a4, float a5, float a6, float a7) {
    float bb = a0; int bd = 0;
    if (a1 < bb) { bb = a1; bd = 1; }
    if (a2 < bb) { bb = a2; bd = 2; }
    if (a3 < bb) { bb = a3; bd = 3; }
    if (a4 < bb) { bb = a4; bd = 4; }
    if (a5 < bb) { bb = a5; bd = 5; }
    if (a6 < bb) { bb = a6; bd = 6; }
    if (a7 < bb) { bb = a7; bd = 7; }
    return bd;
}

// Cross-lane (vertical-ish) neighbor mins, off the GS chain.
// pre[c] = min over the 6 neighbors in lanes +-1, columns c-1..c+1.
__device__ __forceinline__ void build_pre(const float (&d)[32], float (&pre)[32],
                                          int lane)
{
    float m[32];
    #pragma unroll
    for (int c = 0; c < 32; ++c) {
        float u = __shfl_up_sync(FULLM, d[c], 1);
        float v = __shfl_down_sync(FULLM, d[c], 1);
        u = (lane == 0)  ? INF_F : u;
        v = (lane == 31) ? INF_F : v;
        m[c] = fminf(u, v);
    }
    pre[0] = fminf(m[0], m[1]);
    #pragma unroll
    for (int c = 1; c < 31; ++c) pre[c] = fminf(fminf(m[c - 1], m[c]), m[c + 1]);
    pre[31] = fminf(m[30], m[31]);
}

// In-lane GS sweep, low index -> high. Chain: fmin + fadd + fmin (12 cyc/cell).
__device__ __forceinline__ void sweep_lo(float (&d)[32], const float (&w)[32],
                                         const float (&pre)[32], float& chg)
{
    float left = INF_F;
    #pragma unroll
    for (int c = 0; c < 32; ++c) {
        float right = (c < 31) ? d[c + 1] : INF_F;   // pre-update value
        float x  = fminf(pre[c], fminf(left, right));
        float v  = w[c] + x;
        float nd = fminf(d[c], v);
        chg = fmaxf(chg, d[c] - nd);
        d[c] = nd;
        left = nd;
    }
}
// In-lane GS sweep, high index -> low.
__device__ __forceinline__ void sweep_hi(float (&d)[32], const float (&w)[32],
                                         const float (&pre)[32], float& chg)
{
    float right = INF_F;
    #pragma unroll
    for (int c = 31; c >= 0; --c) {
        float left = (c > 0) ? d[c - 1] : INF_F;     // pre-update value
        float x  = fminf(pre[c], fminf(left, right));
        float v  = w[c] + x;
        float nd = fminf(d[c], v);
        chg = fmaxf(chg, d[c] - nd);
        d[c] = nd;
        right = nd;
    }
}

__global__ void __launch_bounds__(32, 1)
bba_kernel(const float* __restrict__ weights,
           const int*   __restrict__ source,
           const int*   __restrict__ target,
           float*       __restrict__ out)
{
    __shared__ float trs[32][33];       // transpose buffer
    __shared__ float wsh[32][33];       // weights (+EPS)
    __shared__ int   nbr[1024];

    const int b    = blockIdx.x;
    const int lane = threadIdx.x;

    // Coalesced weight load -> smem.
    const float* wb = weights + (b << 10);
    #pragma unroll
    for (int r = 0; r < 32; ++r) wsh[r][lane] = wb[(r << 5) + lane] + EPS_F;

    // Zero poisoned output slice (fire-and-forget, coalesced).
    #pragma unroll
    for (int k = 0; k < 32; ++k) out[(b << 10) + (k << 5) + lane] = 0.0f;

    const int sr = source[2 * b + 0];
    const int sc = source[2 * b + 1];
    const int tr = target[2 * b + 0];
    const int tc = target[2 * b + 1];

    __syncwarp();

    // Row-layout and col-layout weights in registers.
    float w[32], wT[32];
    #pragma unroll
    for (int c = 0; c < 32; ++c) w[c]  = wsh[lane][c];   // stride-33: no conflict
    #pragma unroll
    for (int r = 0; r < 32; ++r) wT[r] = wsh[r][lane];   // stride-1:  no conflict

    const float s = wsh[sr][sc];
    float d[32];
    #pragma unroll
    for (int c = 0; c < 32; ++c)
        d[c] = (lane == sr && c == sc) ? s : INF_F;      // dist0

    float pre[32];

    for (;;) {
        float chg = 0.0f;

        // ---- row phase (lane = row): L->R, R->L ----
        build_pre(d, pre, lane);
        sweep_lo(d, w, pre, chg);
        sweep_hi(d, w, pre, chg);

        // transpose to column layout
        #pragma unroll
        for (int c = 0; c < 32; ++c) trs[lane][c] = d[c];
        __syncwarp();
        #pragma unroll
        for (int r = 0; r < 32; ++r) d[r] = trs[r][lane];
        __syncwarp();

        // ---- col phase (lane = col): T->B, B->T ----
        build_pre(d, pre, lane);
        sweep_lo(d, wT, pre, chg);
        sweep_hi(d, wT, pre, chg);

        // transpose back to row layout
        #pragma unroll
        for (int c = 0; c < 32; ++c) trs[lane][c] = d[c];
        __syncwarp();
        #pragma unroll
        for (int r = 0; r < 32; ++r) d[r] = trs[r][lane];
        __syncwarp();

        if (!__any_sync(FULLM, chg > 0.0f)) break;   // zero-change epoch => d*
    }

    // Parallel argmin-neighbor directions, OFFS order:
    // (-1,-1),(-1,0),(-1,1),(0,-1),(0,1),(1,-1),(1,0),(1,1)
    {
        float u[32], v[32];
        #pragma unroll
        for (int c = 0; c < 32; ++c) {
            float uu = __shfl_up_sync(FULLM, d[c], 1);
            float vv = __shfl_down_sync(FULLM, d[c], 1);
            u[c] = (lane == 0)  ? INF_F : uu;
            v[c] = (lane == 31) ? INF_F : vv;
        }
        #pragma unroll
        for (int c = 0; c < 32; ++c) {
            float a0 = (c > 0)  ? u[c - 1] : INF_F;
            float a1 = u[c];
            float a2 = (c < 31) ? u[c + 1] : INF_F;
            float a3 = (c > 0)  ? d[c - 1] : INF_F;
            float a4 = (c < 31) ? d[c + 1] : INF_F;
            float a5 = (c > 0)  ? v[c - 1] : INF_F;
            float a6 = v[c];
            float a7 = (c < 31) ? v[c + 1] : INF_F;
            nbr[(lane << 5) + c] = pick8(a0, a1, a2, a3, a4, a5, a6, a7);
        }
    }
    __syncwarp();

    // Serial backtrack: follow precomputed directions.
    if (lane == 0) {
        const int drs[8] = {-1, -1, -1,  0, 0,  1, 1, 1};
        const int dcs[8] = {-1,  0,  1, -1, 1, -1, 0, 1};
        int cr = tr, cc = tc;
        float* o = out + (b << 10);
        for (int step = 0; step < 1024; ++step) {
            o[(cr << 5) + cc] = 1.0f;
            if (cr == sr && cc == sc) break;
            int k = nbr[(cr << 5) + cc];
            cr += drs[k];
            cc += dcs[k];
        }
    }
}

extern "C" void kernel_launch(void* const* d_in, const int* in_sizes, int n_in,
                              void* d_out, int out_size)
{
    const float* weights = (const float*)d_in[0];
    const int*   source  = (const int*)d_in[1];
    const int*   target  = (const int*)d_in[2];
    float*       out     = (float*)d_out;

    bba_kernel<<<BN, 32>>>(weights, source, target, out);
}